// round 16
// baseline (speedup 1.0000x reference)
#include <cuda_runtime.h>
#include <cuda_fp16.h>
#include <math.h>
#include <stdint.h>

// Problem constants
#define BB   2
#define TT   2048
#define DD   2048
#define NH   16
#define NKV  4
#define HDm  128
#define MROWS (BB*TT)   // 4096
#define GK   2048
#define QROWS (BB*NH*TT)
#define KROWS (BB*NKV*TT)

// Scratch
__device__ float g_rope[TT*128];
__device__ __half g_xh[(long)MROWS*GK];          // fp16 activations (x, then attn ctx)
__device__ __half g_wh[5120L*GK];                // fp16 weights^T
__device__ __half g_qh[(long)QROWS*HDm];         // roped+scaled q
__device__ __half g_kh[(long)KROWS*HDm];         // roped k
__device__ __half g_vt[(long)KROWS*HDm];         // v transposed [bhk][d][t]

// ---------------------------------------------------------------------------
// helpers
// ---------------------------------------------------------------------------
__device__ __forceinline__ uint32_t f2h2(float a, float b) {
    __half2 h = __floats2half2_rn(a, b);
    return *reinterpret_cast<uint32_t*>(&h);
}
__device__ __forceinline__ float rhf(float x) {
    return __half2float(__float2half_rn(x));
}
__device__ __forceinline__ float ex2(float x) {
    float y; asm("ex2.approx.f32 %0, %1;" : "=f"(y) : "f"(x)); return y;
}
__device__ __forceinline__ void mma_f16(float c[4],
                                        uint32_t a0, uint32_t a1, uint32_t a2, uint32_t a3,
                                        uint32_t b0, uint32_t b1) {
    asm volatile(
        "mma.sync.aligned.m16n8k16.row.col.f32.f16.f16.f32 "
        "{%0,%1,%2,%3}, {%4,%5,%6,%7}, {%8,%9}, {%0,%1,%2,%3};\n"
        : "+f"(c[0]), "+f"(c[1]), "+f"(c[2]), "+f"(c[3])
        : "r"(a0), "r"(a1), "r"(a2), "r"(a3), "r"(b0), "r"(b1));
}
__device__ __forceinline__ void ldm_x4(uint32_t& r0, uint32_t& r1,
                                       uint32_t& r2, uint32_t& r3, uint32_t addr) {
    asm volatile("ldmatrix.sync.aligned.m8n8.x4.shared.b16 {%0,%1,%2,%3}, [%4];"
                 : "=r"(r0), "=r"(r1), "=r"(r2), "=r"(r3) : "r"(addr));
}
__device__ __forceinline__ void cpa16(uint32_t dst, const void* src) {
    asm volatile("cp.async.cg.shared.global [%0], [%1], 16;\n"
                 :: "r"(dst), "l"(src) : "memory");
}
#define CP_COMMIT() asm volatile("cp.async.commit_group;\n" ::: "memory")
#define CP_WAIT(n)  asm volatile("cp.async.wait_group %0;\n" :: "n"(n) : "memory")

// ---------------------------------------------------------------------------
// Prep kernels
// ---------------------------------------------------------------------------
// All 4 weight transposes in one launch. bx selects slab.
__global__ void wtrans_all_k(const float* __restrict__ wq, const float* __restrict__ wk,
                             const float* __restrict__ wv, const float* __restrict__ wo,
                             __half* __restrict__ wt)
{
    __shared__ float t[32][33];
    int bx = blockIdx.x;
    const float* w;
    int Nw, nbase, n0;
    if (bx < 64)       { w = wq; Nw = 2048; nbase = 0;    n0 = bx * 32; }
    else if (bx < 80)  { w = wk; Nw = 512;  nbase = 2048; n0 = (bx - 64) * 32; }
    else if (bx < 96)  { w = wv; Nw = 512;  nbase = 2560; n0 = (bx - 80) * 32; }
    else               { w = wo; Nw = 2048; nbase = 3072; n0 = (bx - 96) * 32; }
    int k0 = blockIdx.y * 32;
#pragma unroll
    for (int i = 0; i < 4; i++)
        t[threadIdx.y + i * 8][threadIdx.x] =
            w[(size_t)(k0 + threadIdx.y + i * 8) * Nw + n0 + threadIdx.x];
    __syncthreads();
#pragma unroll
    for (int i = 0; i < 4; i++) {
        int n = n0 + threadIdx.y + i * 8;
        int k = k0 + threadIdx.x;
        wt[(size_t)(nbase + n) * GK + k] = __float2half(t[threadIdx.x][threadIdx.y + i * 8]);
    }
}

__global__ void tohalf_k(const float* __restrict__ src, __half* __restrict__ dst)
{
    int i = blockIdx.x * blockDim.x + threadIdx.x;
    float4 v = ((const float4*)src)[i];
    ((uint2*)dst)[i] = make_uint2(f2h2(v.x, v.y), f2h2(v.z, v.w));
}

__global__ void rope_table_k(float* __restrict__ tab)
{
    int t = blockIdx.x;
    int j = threadIdx.x;
    float inv = exp2f(-(float)j * (13.287712379549449f / 64.0f));
    float ang = (float)t * inv;
    tab[t * 128 + j]      = cosf(ang);
    tab[t * 128 + 64 + j] = sinf(ang);
}

#define SCALE_LOG2E 0.12751744709274227f

// ---------------------------------------------------------------------------
// fp16 QKV GEMM, 3-stage cp.async + ldmatrix, FUSED rope/transpose epilogue.
// BM=BN=128, BK=32, 128 threads, 3 CTAs/SM.
// ---------------------------------------------------------------------------
#define ASTW 20
#define A_SZW (128 * ASTW)
#define GBUFW (2 * A_SZW)
#define GEMM_STAGE_BYTES (GBUFW * 4)
#define GEMM_SMEM_BYTES (3 * GEMM_STAGE_BYTES)   // 61440
#define STP 132                                  // epilogue staging stride (floats)

#define GEMM_ISSUE(kt, s) do { \
    uint32_t As_ = smb + (s) * GEMM_STAGE_BYTES; \
    uint32_t Bs_ = As_ + A_SZW * 4; \
    int k0_ = (kt) * 32; \
    _Pragma("unroll") \
    for (int p = 0; p < 4; p++) { \
        cpa16(As_ + (uint32_t)(((srow + p * 32) * ASTW + scolw) * 4), \
              &Ah[(size_t)(m0 + srow + p * 32) * GK + k0_ + scolh]); \
        cpa16(Bs_ + (uint32_t)(((srow + p * 32) * ASTW + scolw) * 4), \
              &Wh[(size_t)(nrow0 + srow + p * 32) * GK + k0_ + scolh]); \
    } \
    CP_COMMIT(); \
} while (0)

#define GEMM_COMPUTE_TILE(Abase, Bbase) do { \
    _Pragma("unroll") \
    for (int ks = 0; ks < 2; ks++) { \
        uint32_t af[4][4]; \
        _Pragma("unroll") \
        for (int mi = 0; mi < 4; mi++) { \
            int r = warpM * 64 + mi * 16 + lrow + ls8 * 8; \
            ldm_x4(af[mi][0], af[mi][1], af[mi][2], af[mi][3], \
                   (Abase) + (uint32_t)((r * ASTW + ks * 8 + ls16 * 4) * 4)); \
        } \
        _Pragma("unroll") \
        for (int ntp = 0; ntp < 8; ntp += 2) { \
            int n = warpN * 64 + ntp * 8 + lrow + ls16 * 8; \
            uint32_t b00, b01, b10, b11; \
            ldm_x4(b00, b01, b10, b11, \
                   (Bbase) + (uint32_t)((n * ASTW + ks * 8 + ls8 * 4) * 4)); \
            _Pragma("unroll") \
            for (int mi = 0; mi < 4; mi++) { \
                mma_f16(acc[mi][ntp],     af[mi][0], af[mi][1], af[mi][2], af[mi][3], b00, b01); \
                mma_f16(acc[mi][ntp + 1], af[mi][0], af[mi][1], af[mi][2], af[mi][3], b10, b11); \
            } \
        } \
    } \
} while (0)

__global__ void __launch_bounds__(128, 3)
tqkv_k(const __half* __restrict__ Ah, const __half* __restrict__ Wh,
       const float* __restrict__ tab,
       __half* __restrict__ qh, __half* __restrict__ kh, __half* __restrict__ vt)
{
    extern __shared__ uint32_t gsm[];
    uint32_t smb = (uint32_t)__cvta_generic_to_shared(gsm);

    const int bx = blockIdx.x;
    int nrow0, h, Hx, mode;        // mode 0 = rope->qh, 1 = rope->kh, 2 = transpose->vt
    __half* dstg;
    float sc;
    if (bx < 16)      { nrow0 = bx * 128;               h = bx;      Hx = 16; mode = 0; dstg = qh; sc = SCALE_LOG2E; }
    else if (bx < 20) { nrow0 = 2048 + (bx - 16) * 128; h = bx - 16; Hx = 4;  mode = 1; dstg = kh; sc = 1.0f; }
    else              { nrow0 = 2560 + (bx - 20) * 128; h = bx - 20; Hx = 4;  mode = 2; dstg = vt; sc = 1.0f; }

    const int tid = threadIdx.x;
    const int lane = tid & 31;
    const int wid = tid >> 5;
    const int warpM = wid & 1;
    const int warpN = wid >> 1;
    const int m0 = blockIdx.y * 128;

    const int srow = tid >> 2;
    const int scolw = (tid & 3) * 4;
    const int scolh = (tid & 3) * 8;
    const int lrow = lane & 7;
    const int ls8 = (lane >> 3) & 1;
    const int ls16 = (lane >> 4) & 1;

    float acc[4][8][4];
#pragma unroll
    for (int i = 0; i < 4; i++)
#pragma unroll
        for (int jj = 0; jj < 8; jj++)
#pragma unroll
            for (int r = 0; r < 4; r++) acc[i][jj][r] = 0.f;

    const int NKT = GK / 32;
    GEMM_ISSUE(0, 0);
    GEMM_ISSUE(1, 1);

    for (int kt = 0; kt < NKT; kt++) {
        if (kt + 1 < NKT) { CP_WAIT(1); } else { CP_WAIT(0); }
        __syncthreads();
        uint32_t Abase = smb + (kt % 3) * GEMM_STAGE_BYTES;
        uint32_t Bbase = Abase + A_SZW * 4;
        GEMM_COMPUTE_TILE(Abase, Bbase);
        if (kt + 2 < NKT) GEMM_ISSUE(kt + 2, (kt + 2) % 3);
    }
    __syncthreads();   // done reading pipeline smem; reuse as fp32 staging

    // ---- fused epilogue: 2 passes of 64 rows through smem ----
    float* st = (float*)gsm;     // 64 x STP floats = 33792 B < 61440 B
#pragma unroll 1
    for (int pass = 0; pass < 2; pass++) {
        if (warpM == pass) {
#pragma unroll
            for (int mi = 0; mi < 4; mi++) {
                int lr = mi * 16 + (lane >> 2);   // local row in 0..63
#pragma unroll
                for (int nt = 0; nt < 8; nt++) {
                    int c = warpN * 64 + nt * 8 + (lane & 3) * 2;
                    st[lr * STP + c]           = acc[mi][nt][0];
                    st[lr * STP + c + 1]       = acc[mi][nt][1];
                    st[(lr + 8) * STP + c]     = acc[mi][nt][2];
                    st[(lr + 8) * STP + c + 1] = acc[mi][nt][3];
                }
            }
        }
        __syncthreads();

        if (mode == 2) {
            // transpose: thread owns dim d = tid, writes 64 t's as half2
            int d = tid;
            int mbase = m0 + pass * 64;
            int bb = mbase >> 11, tbase = mbase & 2047;
            __half* dp = dstg + ((size_t)(bb * Hx + h) * HDm + d) * TT + tbase;
#pragma unroll
            for (int r = 0; r < 64; r += 2) {
                *(uint32_t*)&dp[r] = f2h2(st[r * STP + d], st[(r + 1) * STP + d]);
            }
        } else {
            // rope: thread owns row r = tid>>1, d-range [(tid&1)*32, +32)
            int r = tid >> 1;
            int m = m0 + pass * 64 + r;
            int bb = m >> 11, t = m & 2047;
            __half* dp = dstg + ((size_t)(bb * Hx + h) * TT + t) * HDm;
            const float* tc = tab + t * 128;
            int d0 = (tid & 1) * 32;
#pragma unroll
            for (int dd = 0; dd < 32; dd += 2) {
                int d = d0 + dd;
                float x1a = st[r * STP + d],      x1b = st[r * STP + d + 1];
                float x2a = st[r * STP + d + 64], x2b = st[r * STP + d + 65];
                float ca = tc[d], cb = tc[d + 1];
                float sa = tc[64 + d], sb = tc[65 + d];
                *(uint32_t*)&dp[d] =
                    f2h2((x1a * ca - x2a * sa) * sc, (x1b * cb - x2b * sb) * sc);
                *(uint32_t*)&dp[d + 64] =
                    f2h2((x2a * ca + x1a * sa) * sc, (x2b * cb + x1b * sb) * sc);
            }
        }
        __syncthreads();
    }
}

// Output projection GEMM (row-major fp32 C), unchanged core.
__global__ void __launch_bounds__(128, 3)
tgemm_k(const __half* __restrict__ Ah, const __half* __restrict__ Wh,
        float* __restrict__ C)
{
    extern __shared__ uint32_t gsm[];
    uint32_t smb = (uint32_t)__cvta_generic_to_shared(gsm);

    const int tid = threadIdx.x;
    const int lane = tid & 31;
    const int wid = tid >> 5;
    const int warpM = wid & 1;
    const int warpN = wid >> 1;
    const int m0 = blockIdx.y * 128;
    const int n0 = blockIdx.x * 128;
    const int nrow0 = 3072 + n0;

    const int srow = tid >> 2;
    const int scolw = (tid & 3) * 4;
    const int scolh = (tid & 3) * 8;
    const int lrow = lane & 7;
    const int ls8 = (lane >> 3) & 1;
    const int ls16 = (lane >> 4) & 1;

    float acc[4][8][4];
#pragma unroll
    for (int i = 0; i < 4; i++)
#pragma unroll
        for (int jj = 0; jj < 8; jj++)
#pragma unroll
            for (int r = 0; r < 4; r++) acc[i][jj][r] = 0.f;

    const int NKT = GK / 32;
    GEMM_ISSUE(0, 0);
    GEMM_ISSUE(1, 1);

    for (int kt = 0; kt < NKT; kt++) {
        if (kt + 1 < NKT) { CP_WAIT(1); } else { CP_WAIT(0); }
        __syncthreads();
        uint32_t Abase = smb + (kt % 3) * GEMM_STAGE_BYTES;
        uint32_t Bbase = Abase + A_SZW * 4;
        GEMM_COMPUTE_TILE(Abase, Bbase);
        if (kt + 2 < NKT) GEMM_ISSUE(kt + 2, (kt + 2) % 3);
    }

#pragma unroll
    for (int mi = 0; mi < 4; mi++) {
        int r1 = m0 + warpM * 64 + mi * 16 + (lane >> 2);
        int r2 = r1 + 8;
#pragma unroll
        for (int nt = 0; nt < 8; nt++) {
            int c = n0 + warpN * 64 + nt * 8 + (lane & 3) * 2;
            *(float2*)&C[(long)r1 * DD + c] = make_float2(acc[mi][nt][0], acc[mi][nt][1]);
            *(float2*)&C[(long)r2 * DD + c] = make_float2(acc[mi][nt][2], acc[mi][nt][3]);
        }
    }
}

// ---------------------------------------------------------------------------
// Causal flash attention (R15, unchanged): BQ=128, BK=64, 256 threads,
// ldmatrix fragments, cp.async double-buffered, fp16 ctx out.
// ---------------------------------------------------------------------------
#define KSTW 68
#define VSTW 36
#define PSTW 36
#define FK_VOFFW (2 * 64 * KSTW)
#define FK_POFFW (FK_VOFFW + 2 * 128 * VSTW)
#define FLASH_SMEM_WORDS (FK_POFFW + 128 * PSTW)
#define FLASH_SMEM_BYTES (FLASH_SMEM_WORDS * 4)

#define FLASH_ISSUE(kt) do { \
    uint32_t Kb_ = smb + (uint32_t)(((kt) & 1) * 64 * KSTW * 4); \
    uint32_t Vb_ = smb + (uint32_t)(FK_VOFFW * 4 + ((kt) & 1) * 128 * VSTW * 4); \
    int kb0_ = (kt) * 64; \
    _Pragma("unroll") \
    for (int s = 0; s < 4; s++) { \
        int slot = tid + s * 256; \
        int krow = slot >> 4, kc16 = slot & 15; \
        cpa16(Kb_ + (uint32_t)(krow * (KSTW * 4) + kc16 * 16), \
              &kg[(long)(kb0_ + krow) * HDm + kc16 * 8]); \
    } \
    _Pragma("unroll") \
    for (int s = 0; s < 4; s++) { \
        int slot = tid + s * 256; \
        int vd = slot >> 3, vc16 = slot & 7; \
        cpa16(Vb_ + (uint32_t)(vd * (VSTW * 4) + vc16 * 16), \
              &vg[(long)vd * TT + kb0_ + vc16 * 8]); \
    } \
    CP_COMMIT(); \
} while (0)

__global__ void __launch_bounds__(256, 1)
flash_k(const __half* __restrict__ Qh, const __half* __restrict__ Kh,
        const __half* __restrict__ Vt, __half* __restrict__ ctxh)
{
    extern __shared__ uint32_t smw[];
    uint32_t smb = (uint32_t)__cvta_generic_to_shared(smw);

    const int tid = threadIdx.x;
    const int lane = tid & 31;
    const int w = tid >> 5;
    const int quad = lane >> 2;
    const int j = lane & 3;
    const int lrow = lane & 7;
    const int ls8 = (lane >> 3) & 1;
    const int ls16 = (lane >> 4) & 1;
    const int qt = gridDim.x - 1 - blockIdx.x;
    const int h  = blockIdx.y;
    const int b  = blockIdx.z;
    const int hk = h >> 2;

    const __half* qg = Qh + ((long)(b * NH  + h ) * TT + qt * 128) * HDm;
    const __half* kg = Kh + ((long)(b * NKV + hk) * TT) * HDm;
    const __half* vg = Vt + ((long)(b * NKV + hk) * HDm) * TT;

    for (int i = tid; i < 2048; i += 256) {
        int r = i >> 4, c = i & 15;
        *(uint4*)&smw[r * KSTW + c * 4] = *(const uint4*)&qg[(long)r * HDm + c * 8];
    }
    __syncthreads();

    uint32_t qf[8][4];
#pragma unroll
    for (int ks = 0; ks < 8; ks++) {
        int r = w * 16 + lrow + ls8 * 8;
        ldm_x4(qf[ks][0], qf[ks][1], qf[ks][2], qf[ks][3],
               smb + (uint32_t)((r * KSTW + ks * 8 + ls16 * 4) * 4));
    }
    __syncthreads();

    uint32_t Ps_b = smb + FK_POFFW * 4;
    uint32_t* Ps = smw + FK_POFFW;

    float oacc[16][4];
#pragma unroll
    for (int nt = 0; nt < 16; nt++)
#pragma unroll
        for (int r = 0; r < 4; r++) oacc[nt][r] = 0.f;

    float m0 = -INFINITY, m1 = -INFINITY, l0 = 0.f, l1 = 0.f;

    const int nkt = 2 * qt + 2;
    const int prow = w * 16 + quad;
    const int qi1 = qt * 128 + prow;
    const int qi2 = qi1 + 8;

    FLASH_ISSUE(0);

    for (int kt = 0; kt < nkt; kt++) {
        uint32_t Kb_b = smb + (uint32_t)((kt & 1) * 64 * KSTW * 4);
        uint32_t Vb_b = smb + (uint32_t)(FK_VOFFW * 4 + (kt & 1) * 128 * VSTW * 4);

        CP_WAIT(0);
        __syncthreads();
        if (kt + 1 < nkt) FLASH_ISSUE(kt + 1);

        float sf[8][4];
#pragma unroll
        for (int nt = 0; nt < 8; nt++)
#pragma unroll
            for (int r = 0; r < 4; r++) sf[nt][r] = 0.f;

#pragma unroll
        for (int ks = 0; ks < 8; ks++) {
#pragma unroll
            for (int ntp = 0; ntp < 8; ntp += 2) {
                int key = ntp * 8 + lrow + ls16 * 8;
                uint32_t b00, b01, b10, b11;
                ldm_x4(b00, b01, b10, b11,
                       Kb_b + (uint32_t)((key * KSTW + ks * 8 + ls8 * 4) * 4));
                mma_f16(sf[ntp],     qf[ks][0], qf[ks][1], qf[ks][2], qf[ks][3], b00, b01);
                mma_f16(sf[ntp + 1], qf[ks][0], qf[ks][1], qf[ks][2], qf[ks][3], b10, b11);
            }
        }

        if (kt >= 2 * qt) {
#pragma unroll
            for (int nt = 0; nt < 8; nt++) {
                int kj = kt * 64 + nt * 8 + 2 * j;
                if (kj     > qi1) sf[nt][0] = -INFINITY;
                if (kj + 1 > qi1) sf[nt][1] = -INFINITY;
                if (kj     > qi2) sf[nt][2] = -INFINITY;
                if (kj + 1 > qi2) sf[nt][3] = -INFINITY;
            }
        }

        float mx0 = -INFINITY, mx1 = -INFINITY;
#pragma unroll
        for (int nt = 0; nt < 8; nt++) {
            mx0 = fmaxf(mx0, fmaxf(sf[nt][0], sf[nt][1]));
            mx1 = fmaxf(mx1, fmaxf(sf[nt][2], sf[nt][3]));
        }
        mx0 = fmaxf(mx0, __shfl_xor_sync(0xffffffffu, mx0, 1));
        mx0 = fmaxf(mx0, __shfl_xor_sync(0xffffffffu, mx0, 2));
        mx1 = fmaxf(mx1, __shfl_xor_sync(0xffffffffu, mx1, 1));
        mx1 = fmaxf(mx1, __shfl_xor_sync(0xffffffffu, mx1, 2));

        float mn0 = fmaxf(m0, mx0);
        float mn1 = fmaxf(m1, mx1);
        float a0 = ex2(m0 - mn0);
        float a1 = ex2(m1 - mn1);
        m0 = mn0; m1 = mn1;

        float s0 = 0.f, s1 = 0.f;
#pragma unroll
        for (int nt = 0; nt < 8; nt++) {
            float p0 = rhf(ex2(sf[nt][0] - mn0));
            float p1 = rhf(ex2(sf[nt][1] - mn0));
            float p2 = rhf(ex2(sf[nt][2] - mn1));
            float p3 = rhf(ex2(sf[nt][3] - mn1));
            s0 += p0 + p1;
            s1 += p2 + p3;
            Ps[prow * PSTW + nt * 4 + j]       = f2h2(p0, p1);
            Ps[(prow + 8) * PSTW + nt * 4 + j] = f2h2(p2, p3);
        }
        s0 += __shfl_xor_sync(0xffffffffu, s0, 1);
        s0 += __shfl_xor_sync(0xffffffffu, s0, 2);
        s1 += __shfl_xor_sync(0xffffffffu, s1, 1);
        s1 += __shfl_xor_sync(0xffffffffu, s1, 2);
        l0 = l0 * a0 + s0;
        l1 = l1 * a1 + s1;

#pragma unroll
        for (int nt = 0; nt < 16; nt++) {
            oacc[nt][0] *= a0; oacc[nt][1] *= a0;
            oacc[nt][2] *= a1; oacc[nt][3] *= a1;
        }
        __syncwarp();

#pragma unroll
        for (int kb = 0; kb < 4; kb++) {
            uint32_t pa0, pa1, pa2, pa3;
            {
                int r = w * 16 + lrow + ls8 * 8;
                ldm_x4(pa0, pa1, pa2, pa3,
                       Ps_b + (uint32_t)((r * PSTW + kb * 8 + ls16 * 4) * 4));
            }
#pragma unroll
            for (int ntp = 0; ntp < 16; ntp += 2) {
                int n = ntp * 8 + lrow + ls16 * 8;
                uint32_t b00, b01, b10, b11;
                ldm_x4(b00, b01, b10, b11,
                       Vb_b + (uint32_t)((n * VSTW + kb * 8 + ls8 * 4) * 4));
                mma_f16(oacc[ntp],     pa0, pa1, pa2, pa3, b00, b01);
                mma_f16(oacc[ntp + 1], pa0, pa1, pa2, pa3, b10, b11);
            }
        }
    }

    float li0 = 1.0f / l0;
    float li1 = 1.0f / l1;
    int t1 = qt * 128 + prow;
    int t2 = t1 + 8;
#pragma unroll
    for (int nt = 0; nt < 16; nt++) {
        int n = h * HDm + nt * 8 + 2 * j;
        *(uint32_t*)&ctxh[((long)(b * TT + t1)) * DD + n] =
            f2h2(oacc[nt][0] * li0, oacc[nt][1] * li0);
        *(uint32_t*)&ctxh[((long)(b * TT + t2)) * DD + n] =
            f2h2(oacc[nt][2] * li1, oacc[nt][3] * li1);
    }
}

// ---------------------------------------------------------------------------
extern "C" void kernel_launch(void* const* d_in, const int* in_sizes, int n_in,
                              void* d_out, int out_size)
{
    const float* x  = (const float*)d_in[0];
    const float* wq = (const float*)d_in[1];
    const float* wk = (const float*)d_in[2];
    const float* wv = (const float*)d_in[3];
    const float* wo = (const float*)d_in[4];
    float* out = (float*)d_out;

    float* tab;
    __half *xh, *wh, *qh, *kh, *vt;
    cudaGetSymbolAddress((void**)&tab, g_rope);
    cudaGetSymbolAddress((void**)&xh,  g_xh);
    cudaGetSymbolAddress((void**)&wh,  g_wh);
    cudaGetSymbolAddress((void**)&qh,  g_qh);
    cudaGetSymbolAddress((void**)&kh,  g_kh);
    cudaGetSymbolAddress((void**)&vt,  g_vt);

    cudaFuncSetAttribute(tqkv_k, cudaFuncAttributeMaxDynamicSharedMemorySize,
                         GEMM_SMEM_BYTES);
    cudaFuncSetAttribute(tgemm_k, cudaFuncAttributeMaxDynamicSharedMemorySize,
                         GEMM_SMEM_BYTES);
    cudaFuncSetAttribute(flash_k, cudaFuncAttributeMaxDynamicSharedMemorySize,
                         FLASH_SMEM_BYTES);

    rope_table_k<<<TT, 64>>>(tab);
    wtrans_all_k<<<dim3(160, 64), dim3(32, 8)>>>(wq, wk, wv, wo, wh);
    tohalf_k<<<(MROWS * GK / 4) / 256, 256>>>(x, xh);

    // Fused QKV projection + rope/transpose epilogue -> qh, kh, vt
    tqkv_k<<<dim3(24, 32), 128, GEMM_SMEM_BYTES>>>(xh, wh, tab, qh, kh, vt);

    // Flash attention -> fp16 ctx (into xh)
    flash_k<<<dim3(TT / 128, NH, BB), 256, FLASH_SMEM_BYTES>>>(qh, kh, vt, xh);

    // Output projection
    tgemm_k<<<dim3(16, 32), 128, GEMM_SMEM_BYTES>>>(xh, wh, out);
}

// round 17
// speedup vs baseline: 1.0524x; 1.0524x over previous
#include <cuda_runtime.h>
#include <cuda_fp16.h>
#include <math.h>
#include <stdint.h>

// Problem constants
#define BB   2
#define TT   2048
#define DD   2048
#define NH   16
#define NKV  4
#define HDm  128
#define MROWS (BB*TT)   // 4096
#define GK   2048
#define QROWS (BB*NH*TT)
#define KROWS (BB*NKV*TT)

// Scratch
__device__ float g_q[BB*NH*TT*HDm];
__device__ float g_k[BB*NKV*TT*HDm];
__device__ float g_v[BB*NKV*TT*HDm];
__device__ float g_rope[TT*128];
__device__ __half g_xh[(long)MROWS*GK];
__device__ __half g_wh[5120L*GK];
__device__ __half g_qh[(long)QROWS*HDm];
__device__ __half g_kh[(long)KROWS*HDm];
__device__ __half g_vt[(long)KROWS*HDm];

// ---------------------------------------------------------------------------
// helpers
// ---------------------------------------------------------------------------
__device__ __forceinline__ uint32_t f2h2(float a, float b) {
    __half2 h = __floats2half2_rn(a, b);
    return *reinterpret_cast<uint32_t*>(&h);
}
__device__ __forceinline__ float rhf(float x) {
    return __half2float(__float2half_rn(x));
}
__device__ __forceinline__ float ex2(float x) {
    float y; asm("ex2.approx.f32 %0, %1;" : "=f"(y) : "f"(x)); return y;
}
__device__ __forceinline__ void mma_f16(float c[4],
                                        uint32_t a0, uint32_t a1, uint32_t a2, uint32_t a3,
                                        uint32_t b0, uint32_t b1) {
    asm volatile(
        "mma.sync.aligned.m16n8k16.row.col.f32.f16.f16.f32 "
        "{%0,%1,%2,%3}, {%4,%5,%6,%7}, {%8,%9}, {%0,%1,%2,%3};\n"
        : "+f"(c[0]), "+f"(c[1]), "+f"(c[2]), "+f"(c[3])
        : "r"(a0), "r"(a1), "r"(a2), "r"(a3), "r"(b0), "r"(b1));
}
__device__ __forceinline__ void ldm_x4(uint32_t& r0, uint32_t& r1,
                                       uint32_t& r2, uint32_t& r3, uint32_t addr) {
    asm volatile("ldmatrix.sync.aligned.m8n8.x4.shared.b16 {%0,%1,%2,%3}, [%4];"
                 : "=r"(r0), "=r"(r1), "=r"(r2), "=r"(r3) : "r"(addr));
}
__device__ __forceinline__ void cpa16(uint32_t dst, const void* src) {
    asm volatile("cp.async.cg.shared.global [%0], [%1], 16;\n"
                 :: "r"(dst), "l"(src) : "memory");
}
#define CP_COMMIT() asm volatile("cp.async.commit_group;\n" ::: "memory")
#define CP_WAIT(n)  asm volatile("cp.async.wait_group %0;\n" :: "n"(n) : "memory")

// ---------------------------------------------------------------------------
// Prep kernels
// ---------------------------------------------------------------------------
// All 4 weight transposes in one launch. bx selects slab.
__global__ void wtrans_all_k(const float* __restrict__ wq, const float* __restrict__ wk,
                             const float* __restrict__ wv, const float* __restrict__ wo,
                             __half* __restrict__ wt)
{
    __shared__ float t[32][33];
    int bx = blockIdx.x;
    const float* w;
    int Nw, nbase, n0;
    if (bx < 64)       { w = wq; Nw = 2048; nbase = 0;    n0 = bx * 32; }
    else if (bx < 80)  { w = wk; Nw = 512;  nbase = 2048; n0 = (bx - 64) * 32; }
    else if (bx < 96)  { w = wv; Nw = 512;  nbase = 2560; n0 = (bx - 80) * 32; }
    else               { w = wo; Nw = 2048; nbase = 3072; n0 = (bx - 96) * 32; }
    int k0 = blockIdx.y * 32;
#pragma unroll
    for (int i = 0; i < 4; i++)
        t[threadIdx.y + i * 8][threadIdx.x] =
            w[(size_t)(k0 + threadIdx.y + i * 8) * Nw + n0 + threadIdx.x];
    __syncthreads();
#pragma unroll
    for (int i = 0; i < 4; i++) {
        int n = n0 + threadIdx.y + i * 8;
        int k = k0 + threadIdx.x;
        wt[(size_t)(nbase + n) * GK + k] = __float2half(t[threadIdx.x][threadIdx.y + i * 8]);
    }
}

__global__ void tohalf_k(const float* __restrict__ src, __half* __restrict__ dst)
{
    int i = blockIdx.x * blockDim.x + threadIdx.x;
    float4 v = ((const float4*)src)[i];
    ((uint2*)dst)[i] = make_uint2(f2h2(v.x, v.y), f2h2(v.z, v.w));
}

__global__ void rope_table_k(float* __restrict__ tab)
{
    int t = blockIdx.x;
    int j = threadIdx.x;
    float inv = exp2f(-(float)j * (13.287712379549449f / 64.0f));
    float ang = (float)t * inv;
    tab[t * 128 + j]      = cosf(ang);
    tab[t * 128 + 64 + j] = sinf(ang);
}

#define SCALE_LOG2E 0.12751744709274227f
__global__ void ropeh2_k(const float* __restrict__ qp, const float* __restrict__ kp,
                         const float* __restrict__ tab,
                         __half* __restrict__ qh, __half* __restrict__ kh)
{
    int row = blockIdx.x * 4 + (threadIdx.x >> 6);
    int j = threadIdx.x & 63;
    const float* src;
    __half* dst;
    float sc;
    int r;
    if (row < QROWS) { src = qp; dst = qh; r = row;         sc = SCALE_LOG2E; }
    else             { src = kp; dst = kh; r = row - QROWS; sc = 1.0f; }
    int t = r & 2047;
    float c = tab[t * 128 + j];
    float s = tab[t * 128 + 64 + j];
    const float* p = src + (long)r * 128;
    float x1 = p[j], x2 = p[j + 64];
    dst[(long)r * 128 + j]      = __float2half((x1 * c - x2 * s) * sc);
    dst[(long)r * 128 + j + 64] = __float2half((x2 * c + x1 * s) * sc);
}

__global__ void vtrans_k(const float* __restrict__ v, __half* __restrict__ vt)
{
    __shared__ float t[32][33];
    int t0 = blockIdx.x * 32, d0 = blockIdx.y * 32, bhk = blockIdx.z;
    const float* src = v + (size_t)bhk * TT * HDm;
    __half* dst = vt + (size_t)bhk * HDm * TT;
#pragma unroll
    for (int i = 0; i < 4; i++)
        t[threadIdx.y + i * 8][threadIdx.x] =
            src[(size_t)(t0 + threadIdx.y + i * 8) * HDm + d0 + threadIdx.x];
    __syncthreads();
#pragma unroll
    for (int i = 0; i < 4; i++) {
        int d = d0 + threadIdx.y + i * 8;
        dst[(size_t)d * TT + t0 + threadIdx.x] =
            __float2half(t[threadIdx.x][threadIdx.y + i * 8]);
    }
}

// ---------------------------------------------------------------------------
// fp16 GEMM, 3-stage cp.async pipeline + ldmatrix fragments.
// BM=BN=128, BK=32, 128 threads, 3 CTAs/SM.
// ---------------------------------------------------------------------------
#define ASTW 20
#define A_SZW (128 * ASTW)
#define GBUFW (2 * A_SZW)
#define GEMM_STAGE_BYTES (GBUFW * 4)
#define GEMM_SMEM_BYTES (3 * GEMM_STAGE_BYTES)

#define GEMM_ISSUE(kt, s) do { \
    uint32_t As_ = smb + (s) * GEMM_STAGE_BYTES; \
    uint32_t Bs_ = As_ + A_SZW * 4; \
    int k0_ = (kt) * 32; \
    _Pragma("unroll") \
    for (int p = 0; p < 4; p++) { \
        cpa16(As_ + (uint32_t)(((srow + p * 32) * ASTW + scolw) * 4), \
              &Ah[(size_t)(m0 + srow + p * 32) * GK + k0_ + scolh]); \
        cpa16(Bs_ + (uint32_t)(((srow + p * 32) * ASTW + scolw) * 4), \
              &Wh[(size_t)(nrow0 + srow + p * 32) * GK + k0_ + scolh]); \
    } \
    CP_COMMIT(); \
} while (0)

#define GEMM_COMPUTE_TILE(Abase, Bbase) do { \
    _Pragma("unroll") \
    for (int ks = 0; ks < 2; ks++) { \
        uint32_t af[4][4]; \
        _Pragma("unroll") \
        for (int mi = 0; mi < 4; mi++) { \
            int r = warpM * 64 + mi * 16 + lrow + ls8 * 8; \
            ldm_x4(af[mi][0], af[mi][1], af[mi][2], af[mi][3], \
                   (Abase) + (uint32_t)((r * ASTW + ks * 8 + ls16 * 4) * 4)); \
        } \
        _Pragma("unroll") \
        for (int ntp = 0; ntp < 8; ntp += 2) { \
            int n = warpN * 64 + ntp * 8 + lrow + ls16 * 8; \
            uint32_t b00, b01, b10, b11; \
            ldm_x4(b00, b01, b10, b11, \
                   (Bbase) + (uint32_t)((n * ASTW + ks * 8 + ls8 * 4) * 4)); \
            _Pragma("unroll") \
            for (int mi = 0; mi < 4; mi++) { \
                mma_f16(acc[mi][ntp],     af[mi][0], af[mi][1], af[mi][2], af[mi][3], b00, b01); \
                mma_f16(acc[mi][ntp + 1], af[mi][0], af[mi][1], af[mi][2], af[mi][3], b10, b11); \
            } \
        } \
    } \
} while (0)

__global__ void __launch_bounds__(128, 3)
tqkv_k(const __half* __restrict__ Ah, const __half* __restrict__ Wh,
       float* __restrict__ qo, float* __restrict__ ko, float* __restrict__ vo)
{
    extern __shared__ uint32_t gsm[];
    uint32_t smb = (uint32_t)__cvta_generic_to_shared(gsm);

    const int bx = blockIdx.x;
    float* C;
    int n0, nrow0, Hx;
    if (bx < 16)      { C = qo; n0 = bx * 128;        nrow0 = n0;        Hx = 16; }
    else if (bx < 20) { C = ko; n0 = (bx - 16) * 128; nrow0 = 2048 + n0; Hx = 4;  }
    else              { C = vo; n0 = (bx - 20) * 128; nrow0 = 2560 + n0; Hx = 4;  }

    const int tid = threadIdx.x;
    const int lane = tid & 31;
    const int wid = tid >> 5;
    const int warpM = wid & 1;
    const int warpN = wid >> 1;
    const int m0 = blockIdx.y * 128;

    const int srow = tid >> 2;
    const int scolw = (tid & 3) * 4;
    const int scolh = (tid & 3) * 8;
    const int lrow = lane & 7;
    const int ls8 = (lane >> 3) & 1;
    const int ls16 = (lane >> 4) & 1;

    float acc[4][8][4];
#pragma unroll
    for (int i = 0; i < 4; i++)
#pragma unroll
        for (int jj = 0; jj < 8; jj++)
#pragma unroll
            for (int r = 0; r < 4; r++) acc[i][jj][r] = 0.f;

    const int NKT = GK / 32;
    GEMM_ISSUE(0, 0);
    GEMM_ISSUE(1, 1);

    for (int kt = 0; kt < NKT; kt++) {
        if (kt + 1 < NKT) { CP_WAIT(1); } else { CP_WAIT(0); }
        __syncthreads();
        uint32_t Abase = smb + (kt % 3) * GEMM_STAGE_BYTES;
        uint32_t Bbase = Abase + A_SZW * 4;
        GEMM_COMPUTE_TILE(Abase, Bbase);
        if (kt + 2 < NKT) GEMM_ISSUE(kt + 2, (kt + 2) % 3);
    }

#pragma unroll
    for (int mi = 0; mi < 4; mi++) {
        int r1 = m0 + warpM * 64 + mi * 16 + (lane >> 2);
        int r2 = r1 + 8;
#pragma unroll
        for (int nt = 0; nt < 8; nt++) {
            int c = n0 + warpN * 64 + nt * 8 + (lane & 3) * 2;
            int h = c >> 7, d = c & 127;
            int b1 = r1 >> 11, t1 = r1 & 2047;
            int b2 = r2 >> 11, t2 = r2 & 2047;
            *(float2*)&C[((long)(b1 * Hx + h) * TT + t1) * HDm + d] =
                make_float2(acc[mi][nt][0], acc[mi][nt][1]);
            *(float2*)&C[((long)(b2 * Hx + h) * TT + t2) * HDm + d] =
                make_float2(acc[mi][nt][2], acc[mi][nt][3]);
        }
    }
}

__global__ void __launch_bounds__(128, 3)
tgemm_k(const __half* __restrict__ Ah, const __half* __restrict__ Wh,
        float* __restrict__ C)
{
    extern __shared__ uint32_t gsm[];
    uint32_t smb = (uint32_t)__cvta_generic_to_shared(gsm);

    const int tid = threadIdx.x;
    const int lane = tid & 31;
    const int wid = tid >> 5;
    const int warpM = wid & 1;
    const int warpN = wid >> 1;
    const int m0 = blockIdx.y * 128;
    const int n0 = blockIdx.x * 128;
    const int nrow0 = 3072 + n0;

    const int srow = tid >> 2;
    const int scolw = (tid & 3) * 4;
    const int scolh = (tid & 3) * 8;
    const int lrow = lane & 7;
    const int ls8 = (lane >> 3) & 1;
    const int ls16 = (lane >> 4) & 1;

    float acc[4][8][4];
#pragma unroll
    for (int i = 0; i < 4; i++)
#pragma unroll
        for (int jj = 0; jj < 8; jj++)
#pragma unroll
            for (int r = 0; r < 4; r++) acc[i][jj][r] = 0.f;

    const int NKT = GK / 32;
    GEMM_ISSUE(0, 0);
    GEMM_ISSUE(1, 1);

    for (int kt = 0; kt < NKT; kt++) {
        if (kt + 1 < NKT) { CP_WAIT(1); } else { CP_WAIT(0); }
        __syncthreads();
        uint32_t Abase = smb + (kt % 3) * GEMM_STAGE_BYTES;
        uint32_t Bbase = Abase + A_SZW * 4;
        GEMM_COMPUTE_TILE(Abase, Bbase);
        if (kt + 2 < NKT) GEMM_ISSUE(kt + 2, (kt + 2) % 3);
    }

#pragma unroll
    for (int mi = 0; mi < 4; mi++) {
        int r1 = m0 + warpM * 64 + mi * 16 + (lane >> 2);
        int r2 = r1 + 8;
#pragma unroll
        for (int nt = 0; nt < 8; nt++) {
            int c = n0 + warpN * 64 + nt * 8 + (lane & 3) * 2;
            *(float2*)&C[(long)r1 * DD + c] = make_float2(acc[mi][nt][0], acc[mi][nt][1]);
            *(float2*)&C[(long)r2 * DD + c] = make_float2(acc[mi][nt][2], acc[mi][nt][3]);
        }
    }
}

// ---------------------------------------------------------------------------
// Causal flash attention (R15): BQ=128, BK=64, 256 threads, ldmatrix fragments.
// ---------------------------------------------------------------------------
#define KSTW 68
#define VSTW 36
#define PSTW 36
#define FK_VOFFW (2 * 64 * KSTW)
#define FK_POFFW (FK_VOFFW + 2 * 128 * VSTW)
#define FLASH_SMEM_WORDS (FK_POFFW + 128 * PSTW)
#define FLASH_SMEM_BYTES (FLASH_SMEM_WORDS * 4)

#define FLASH_ISSUE(kt) do { \
    uint32_t Kb_ = smb + (uint32_t)(((kt) & 1) * 64 * KSTW * 4); \
    uint32_t Vb_ = smb + (uint32_t)(FK_VOFFW * 4 + ((kt) & 1) * 128 * VSTW * 4); \
    int kb0_ = (kt) * 64; \
    _Pragma("unroll") \
    for (int s = 0; s < 4; s++) { \
        int slot = tid + s * 256; \
        int krow = slot >> 4, kc16 = slot & 15; \
        cpa16(Kb_ + (uint32_t)(krow * (KSTW * 4) + kc16 * 16), \
              &kg[(long)(kb0_ + krow) * HDm + kc16 * 8]); \
    } \
    _Pragma("unroll") \
    for (int s = 0; s < 4; s++) { \
        int slot = tid + s * 256; \
        int vd = slot >> 3, vc16 = slot & 7; \
        cpa16(Vb_ + (uint32_t)(vd * (VSTW * 4) + vc16 * 16), \
              &vg[(long)vd * TT + kb0_ + vc16 * 8]); \
    } \
    CP_COMMIT(); \
} while (0)

__global__ void __launch_bounds__(256, 1)
flash_k(const __half* __restrict__ Qh, const __half* __restrict__ Kh,
        const __half* __restrict__ Vt, __half* __restrict__ ctxh)
{
    extern __shared__ uint32_t smw[];
    uint32_t smb = (uint32_t)__cvta_generic_to_shared(smw);

    const int tid = threadIdx.x;
    const int lane = tid & 31;
    const int w = tid >> 5;
    const int quad = lane >> 2;
    const int j = lane & 3;
    const int lrow = lane & 7;
    const int ls8 = (lane >> 3) & 1;
    const int ls16 = (lane >> 4) & 1;
    const int qt = gridDim.x - 1 - blockIdx.x;
    const int h  = blockIdx.y;
    const int b  = blockIdx.z;
    const int hk = h >> 2;

    const __half* qg = Qh + ((long)(b * NH  + h ) * TT + qt * 128) * HDm;
    const __half* kg = Kh + ((long)(b * NKV + hk) * TT) * HDm;
    const __half* vg = Vt + ((long)(b * NKV + hk) * HDm) * TT;

    for (int i = tid; i < 2048; i += 256) {
        int r = i >> 4, c = i & 15;
        *(uint4*)&smw[r * KSTW + c * 4] = *(const uint4*)&qg[(long)r * HDm + c * 8];
    }
    __syncthreads();

    uint32_t qf[8][4];
#pragma unroll
    for (int ks = 0; ks < 8; ks++) {
        int r = w * 16 + lrow + ls8 * 8;
        ldm_x4(qf[ks][0], qf[ks][1], qf[ks][2], qf[ks][3],
               smb + (uint32_t)((r * KSTW + ks * 8 + ls16 * 4) * 4));
    }
    __syncthreads();

    uint32_t Ps_b = smb + FK_POFFW * 4;
    uint32_t* Ps = smw + FK_POFFW;

    float oacc[16][4];
#pragma unroll
    for (int nt = 0; nt < 16; nt++)
#pragma unroll
        for (int r = 0; r < 4; r++) oacc[nt][r] = 0.f;

    float m0 = -INFINITY, m1 = -INFINITY, l0 = 0.f, l1 = 0.f;

    const int nkt = 2 * qt + 2;
    const int prow = w * 16 + quad;
    const int qi1 = qt * 128 + prow;
    const int qi2 = qi1 + 8;

    FLASH_ISSUE(0);

    for (int kt = 0; kt < nkt; kt++) {
        uint32_t Kb_b = smb + (uint32_t)((kt & 1) * 64 * KSTW * 4);
        uint32_t Vb_b = smb + (uint32_t)(FK_VOFFW * 4 + (kt & 1) * 128 * VSTW * 4);

        CP_WAIT(0);
        __syncthreads();
        if (kt + 1 < nkt) FLASH_ISSUE(kt + 1);

        float sf[8][4];
#pragma unroll
        for (int nt = 0; nt < 8; nt++)
#pragma unroll
            for (int r = 0; r < 4; r++) sf[nt][r] = 0.f;

#pragma unroll
        for (int ks = 0; ks < 8; ks++) {
#pragma unroll
            for (int ntp = 0; ntp < 8; ntp += 2) {
                int key = ntp * 8 + lrow + ls16 * 8;
                uint32_t b00, b01, b10, b11;
                ldm_x4(b00, b01, b10, b11,
                       Kb_b + (uint32_t)((key * KSTW + ks * 8 + ls8 * 4) * 4));
                mma_f16(sf[ntp],     qf[ks][0], qf[ks][1], qf[ks][2], qf[ks][3], b00, b01);
                mma_f16(sf[ntp + 1], qf[ks][0], qf[ks][1], qf[ks][2], qf[ks][3], b10, b11);
            }
        }

        if (kt >= 2 * qt) {
#pragma unroll
            for (int nt = 0; nt < 8; nt++) {
                int kj = kt * 64 + nt * 8 + 2 * j;
                if (kj     > qi1) sf[nt][0] = -INFINITY;
                if (kj + 1 > qi1) sf[nt][1] = -INFINITY;
                if (kj     > qi2) sf[nt][2] = -INFINITY;
                if (kj + 1 > qi2) sf[nt][3] = -INFINITY;
            }
        }

        float mx0 = -INFINITY, mx1 = -INFINITY;
#pragma unroll
        for (int nt = 0; nt < 8; nt++) {
            mx0 = fmaxf(mx0, fmaxf(sf[nt][0], sf[nt][1]));
            mx1 = fmaxf(mx1, fmaxf(sf[nt][2], sf[nt][3]));
        }
        mx0 = fmaxf(mx0, __shfl_xor_sync(0xffffffffu, mx0, 1));
        mx0 = fmaxf(mx0, __shfl_xor_sync(0xffffffffu, mx0, 2));
        mx1 = fmaxf(mx1, __shfl_xor_sync(0xffffffffu, mx1, 1));
        mx1 = fmaxf(mx1, __shfl_xor_sync(0xffffffffu, mx1, 2));

        float mn0 = fmaxf(m0, mx0);
        float mn1 = fmaxf(m1, mx1);
        float a0 = ex2(m0 - mn0);
        float a1 = ex2(m1 - mn1);
        m0 = mn0; m1 = mn1;

        float s0 = 0.f, s1 = 0.f;
#pragma unroll
        for (int nt = 0; nt < 8; nt++) {
            float p0 = rhf(ex2(sf[nt][0] - mn0));
            float p1 = rhf(ex2(sf[nt][1] - mn0));
            float p2 = rhf(ex2(sf[nt][2] - mn1));
            float p3 = rhf(ex2(sf[nt][3] - mn1));
            s0 += p0 + p1;
            s1 += p2 + p3;
            Ps[prow * PSTW + nt * 4 + j]       = f2h2(p0, p1);
            Ps[(prow + 8) * PSTW + nt * 4 + j] = f2h2(p2, p3);
        }
        s0 += __shfl_xor_sync(0xffffffffu, s0, 1);
        s0 += __shfl_xor_sync(0xffffffffu, s0, 2);
        s1 += __shfl_xor_sync(0xffffffffu, s1, 1);
        s1 += __shfl_xor_sync(0xffffffffu, s1, 2);
        l0 = l0 * a0 + s0;
        l1 = l1 * a1 + s1;

#pragma unroll
        for (int nt = 0; nt < 16; nt++) {
            oacc[nt][0] *= a0; oacc[nt][1] *= a0;
            oacc[nt][2] *= a1; oacc[nt][3] *= a1;
        }
        __syncwarp();

#pragma unroll
        for (int kb = 0; kb < 4; kb++) {
            uint32_t pa0, pa1, pa2, pa3;
            {
                int r = w * 16 + lrow + ls8 * 8;
                ldm_x4(pa0, pa1, pa2, pa3,
                       Ps_b + (uint32_t)((r * PSTW + kb * 8 + ls16 * 4) * 4));
            }
#pragma unroll
            for (int ntp = 0; ntp < 16; ntp += 2) {
                int n = ntp * 8 + lrow + ls16 * 8;
                uint32_t b00, b01, b10, b11;
                ldm_x4(b00, b01, b10, b11,
                       Vb_b + (uint32_t)((n * VSTW + kb * 8 + ls8 * 4) * 4));
                mma_f16(oacc[ntp],     pa0, pa1, pa2, pa3, b00, b01);
                mma_f16(oacc[ntp + 1], pa0, pa1, pa2, pa3, b10, b11);
            }
        }
    }

    float li0 = 1.0f / l0;
    float li1 = 1.0f / l1;
    int t1 = qt * 128 + prow;
    int t2 = t1 + 8;
#pragma unroll
    for (int nt = 0; nt < 16; nt++) {
        int n = h * HDm + nt * 8 + 2 * j;
        *(uint32_t*)&ctxh[((long)(b * TT + t1)) * DD + n] =
            f2h2(oacc[nt][0] * li0, oacc[nt][1] * li0);
        *(uint32_t*)&ctxh[((long)(b * TT + t2)) * DD + n] =
            f2h2(oacc[nt][2] * li1, oacc[nt][3] * li1);
    }
}

// ---------------------------------------------------------------------------
extern "C" void kernel_launch(void* const* d_in, const int* in_sizes, int n_in,
                              void* d_out, int out_size)
{
    const float* x  = (const float*)d_in[0];
    const float* wq = (const float*)d_in[1];
    const float* wk = (const float*)d_in[2];
    const float* wv = (const float*)d_in[3];
    const float* wo = (const float*)d_in[4];
    float* out = (float*)d_out;

    float *q, *k, *v, *tab;
    __half *xh, *wh, *qh, *kh, *vt;
    cudaGetSymbolAddress((void**)&q,   g_q);
    cudaGetSymbolAddress((void**)&k,   g_k);
    cudaGetSymbolAddress((void**)&v,   g_v);
    cudaGetSymbolAddress((void**)&tab, g_rope);
    cudaGetSymbolAddress((void**)&xh,  g_xh);
    cudaGetSymbolAddress((void**)&wh,  g_wh);
    cudaGetSymbolAddress((void**)&qh,  g_qh);
    cudaGetSymbolAddress((void**)&kh,  g_kh);
    cudaGetSymbolAddress((void**)&vt,  g_vt);

    cudaFuncSetAttribute(tqkv_k, cudaFuncAttributeMaxDynamicSharedMemorySize,
                         GEMM_SMEM_BYTES);
    cudaFuncSetAttribute(tgemm_k, cudaFuncAttributeMaxDynamicSharedMemorySize,
                         GEMM_SMEM_BYTES);
    cudaFuncSetAttribute(flash_k, cudaFuncAttributeMaxDynamicSharedMemorySize,
                         FLASH_SMEM_BYTES);

    rope_table_k<<<TT, 64>>>(tab);
    wtrans_all_k<<<dim3(160, 64), dim3(32, 8)>>>(wq, wk, wv, wo, wh);
    tohalf_k<<<(MROWS * GK / 4) / 256, 256>>>(x, xh);

    tqkv_k<<<dim3(24, 32), 128, GEMM_SMEM_BYTES>>>(xh, wh, q, k, v);

    ropeh2_k<<<(QROWS + KROWS) / 4, 256>>>(q, k, tab, qh, kh);
    vtrans_k<<<dim3(TT / 32, HDm / 32, BB * NKV), dim3(32, 8)>>>(v, vt);

    flash_k<<<dim3(TT / 128, NH, BB), 256, FLASH_SMEM_BYTES>>>(qh, kh, vt, xh);

    tgemm_k<<<dim3(16, 32), 128, GEMM_SMEM_BYTES>>>(xh, wh, out);
}